// round 17
// baseline (speedup 1.0000x reference)
#include <cuda_runtime.h>
#include <cstdint>

// TraitSimilarity via warp-level mma.sync tf32 (baseline PTX, sm_80+).
// Gram products per 8-sample block: P = Phi^T Phi (cos), H = Thi^T Thi,
// L = Tlo^T Thi;  Gt = H + L + L^T (split-tf32, lo*lo dropped).
// Fragment trick: per-lane loads e[u][c] = X[s + q + 4u][g + 8c]
// (q=lane%4, g=lane/4) serve BOTH A and B fragments of m16n8k8 -> zero
// duplication, no smem, no shuffles in the hot loop.

#define NCTA   592   // 4 CTAs/SM * 148 SMs -> one clean wave at 128 regs
#define TPB    128
#define NWARPS (NCTA * 4)
#define NOUT   3104  // P(1024) H(1024) L(1024) cs(32)

__device__ float g_part[NOUT * NCTA];   // TRANSPOSED: [o][cta]
__device__ float g_red[NOUT];
__device__ int   g_ctr;                 // zero-init; reset by last block

static __device__ __forceinline__ uint32_t f2tf(float x) {
    uint32_t r; asm("cvt.rna.tf32.f32 %0, %1;" : "=r"(r) : "f"(x));
    return r;
}
static __device__ __forceinline__ void mma8(float* d,
        uint32_t a0, uint32_t a1, uint32_t a2, uint32_t a3,
        uint32_t b0, uint32_t b1) {
    asm volatile(
        "mma.sync.aligned.m16n8k8.row.col.f32.tf32.tf32.f32 "
        "{%0,%1,%2,%3}, {%4,%5,%6,%7}, {%8,%9}, {%0,%1,%2,%3};"
        : "+f"(d[0]), "+f"(d[1]), "+f"(d[2]), "+f"(d[3])
        : "r"(a0), "r"(a1), "r"(a2), "r"(a3), "r"(b0), "r"(b1));
}
// A-tile mt (traits 16mt..16mt+15), B-tile nt (traits 8nt..8nt+7)
#define MMA_T(dst, A, mt, B, nt) \
    mma8(dst, A[2*(mt)], A[2*(mt)+1], A[4+2*(mt)], A[4+2*(mt)+1], B[(nt)], B[4+(nt)])

__global__ void __launch_bounds__(TPB, 4)
gram_mma(const float* __restrict__ yp, const float* __restrict__ yt, int nblocks) {
    __shared__ float smg[3][32][33];
    __shared__ float smcs[32];

    const int tid = threadIdx.x, wid = tid >> 5, lane = tid & 31;
    const int g = lane >> 2, q = lane & 3;
    const int W = blockIdx.x * 4 + wid;
    const int laneoff = q * 32 + g;     // float offset within 8x32 block

    // accumulators: 6 symmetric tiles for P and H, 8 full tiles for L
    float accP[6][4], accH[6][4], accL[8][4];
#pragma unroll
    for (int i = 0; i < 6; ++i)
#pragma unroll
        for (int j = 0; j < 4; ++j) { accP[i][j] = 0.f; accH[i][j] = 0.f; }
#pragma unroll
    for (int i = 0; i < 8; ++i)
#pragma unroll
        for (int j = 0; j < 4; ++j) accL[i][j] = 0.f;
    float cs[4] = {0.f, 0.f, 0.f, 0.f};

    for (int b = W; b < nblocks; b += NWARPS) {
        const float* P = yp + (size_t)b * 256 + laneoff;
        const float* T = yt + (size_t)b * 256 + laneoff;
        float rp[8], rt[8];
#pragma unroll
        for (int u = 0; u < 2; ++u)
#pragma unroll
            for (int c = 0; c < 4; ++c) {
                rp[u * 4 + c] = P[u * 128 + c * 8];
                rt[u * 4 + c] = T[u * 128 + c * 8];
            }

        uint32_t ph[8], th[8], tl[8];
#pragma unroll
        for (int i = 0; i < 8; ++i) ph[i] = f2tf(rp[i]);
#pragma unroll
        for (int i = 0; i < 8; ++i) {
            th[i] = f2tf(rt[i]);
            tl[i] = f2tf(rt[i] - __uint_as_float(th[i]));
        }
#pragma unroll
        for (int c = 0; c < 4; ++c) { cs[c] += rt[c]; cs[c] += rt[4 + c]; }

        // symmetric products: tiles (0,0)(0,1)(0,2)(0,3)(1,2)(1,3)
        MMA_T(accP[0], ph, 0, ph, 0);  MMA_T(accH[0], th, 0, th, 0);
        MMA_T(accP[1], ph, 0, ph, 1);  MMA_T(accH[1], th, 0, th, 1);
        MMA_T(accP[2], ph, 0, ph, 2);  MMA_T(accH[2], th, 0, th, 2);
        MMA_T(accP[3], ph, 0, ph, 3);  MMA_T(accH[3], th, 0, th, 3);
        MMA_T(accP[4], ph, 1, ph, 2);  MMA_T(accH[4], th, 1, th, 2);
        MMA_T(accP[5], ph, 1, ph, 3);  MMA_T(accH[5], th, 1, th, 3);
        // L = Tlo^T Thi, all 8 tiles
        MMA_T(accL[0], tl, 0, th, 0);  MMA_T(accL[1], tl, 0, th, 1);
        MMA_T(accL[2], tl, 0, th, 2);  MMA_T(accL[3], tl, 0, th, 3);
        MMA_T(accL[4], tl, 1, th, 0);  MMA_T(accL[5], tl, 1, th, 1);
        MMA_T(accL[6], tl, 1, th, 2);  MMA_T(accL[7], tl, 1, th, 3);
    }

    // ---------------- epilogue ----------------
    for (int o = tid; o < 3 * 32 * 33; o += TPB) ((float*)smg)[o] = 0.f;
    if (tid < 32) smcs[tid] = 0.f;
    __syncthreads();

    // quad-reduce colsum: trait = g + 8c, owned by q==0
#pragma unroll
    for (int c = 0; c < 4; ++c) {
        cs[c] += __shfl_xor_sync(0xffffffffu, cs[c], 1);
        cs[c] += __shfl_xor_sync(0xffffffffu, cs[c], 2);
    }

    const int SYM_MT[6] = {0, 0, 0, 0, 1, 1};
    const int SYM_NT[6] = {0, 1, 2, 3, 2, 3};
    for (int r = 0; r < 4; ++r) {
        if (wid == r) {
#pragma unroll
            for (int i = 0; i < 6; ++i) {
                const int r0 = 16 * SYM_MT[i] + g, c0 = 8 * SYM_NT[i] + 2 * q;
                smg[0][r0][c0]     += accP[i][0];
                smg[0][r0][c0 + 1] += accP[i][1];
                smg[0][r0 + 8][c0]     += accP[i][2];
                smg[0][r0 + 8][c0 + 1] += accP[i][3];
                smg[1][r0][c0]     += accH[i][0];
                smg[1][r0][c0 + 1] += accH[i][1];
                smg[1][r0 + 8][c0]     += accH[i][2];
                smg[1][r0 + 8][c0 + 1] += accH[i][3];
            }
#pragma unroll
            for (int i = 0; i < 8; ++i) {
                const int r0 = 16 * (i >> 2) + g, c0 = 8 * (i & 3) + 2 * q;
                smg[2][r0][c0]     += accL[i][0];
                smg[2][r0][c0 + 1] += accL[i][1];
                smg[2][r0 + 8][c0]     += accL[i][2];
                smg[2][r0 + 8][c0 + 1] += accL[i][3];
            }
            if (q == 0)
#pragma unroll
                for (int c = 0; c < 4; ++c) smcs[g + 8 * c] += cs[c];
        }
        __syncthreads();
    }

    // transposed partial store: g_part[o][cta] (coalesced for the reducer)
    float* outp = g_part + blockIdx.x;
    for (int o = tid; o < 3072; o += TPB) {
        const int p = o >> 10, rc = o & 1023;
        outp[(size_t)o * NCTA] = smg[p][rc >> 5][rc & 31];
    }
    if (tid < 32) outp[(size_t)(3072 + tid) * NCTA] = smcs[tid];
}

// ------- fused reduce + finalize (threadfence-reduction, last block) -------
// Each warp owns one output o; lanes sweep ctas coalesced, shfl-tree reduce
// (fixed order -> deterministic). Last-arriving block computes the scalar.
__global__ void __launch_bounds__(TPB, 8)
reduce_final(float* __restrict__ out, float invN) {
    __shared__ int s_old;
    const int warp = threadIdx.x >> 5, lane = threadIdx.x & 31;
    const int o = blockIdx.x * 4 + warp;   // grid 776 -> o in [0, 3104)

    float s = 0.f;
    const float* p = g_part + (size_t)o * NCTA;
#pragma unroll 4
    for (int c = lane; c < NCTA; c += 32) s += p[c];
#pragma unroll
    for (int d = 16; d > 0; d >>= 1)
        s += __shfl_down_sync(0xffffffffu, s, d);
    if (lane == 0) g_red[o] = s;

    __threadfence();
    __syncthreads();
    if (threadIdx.x == 0) s_old = atomicAdd(&g_ctr, 1);
    __syncthreads();
    if (s_old != (int)gridDim.x - 1) return;

    // last block: all g_red writes are visible after the acquire fence
    __threadfence();
    __shared__ float pn[32], csm[32];
    if (threadIdx.x < 32) {
        const int ln = threadIdx.x;
        pn[ln]  = sqrtf(g_red[ln * 32 + ln]);   // sqrt(P[j][j])
        csm[ln] = g_red[3072 + ln];
        __syncwarp();

        float sum = 0.f;
        for (int idx = ln; idx < 465; idx += 32) {  // pairs 1 <= j < k < 32
            int j = 1, rem = idx;
            while (rem >= 31 - j) { rem -= 31 - j; ++j; }
            const int k = j + 1 + rem;
            const float gt = g_red[1024 + j * 32 + k]          // H[j][k]
                           + g_red[2048 + j * 32 + k]          // L[j][k]
                           + g_red[2048 + k * 32 + j];         // L[k][j]
            const float num  = gt - csm[j] * csm[k] * invN;
            const float cosv = g_red[j * 32 + k] / fmaxf(pn[j] * pn[k], 1e-8f);
            if (num >= 0.f) sum += 1.f - cosv;
        }
#pragma unroll
        for (int d = 16; d > 0; d >>= 1)
            sum += __shfl_down_sync(0xffffffffu, sum, d);
        if (ln == 0) {
            out[0] = sum / 465.0f;
            g_ctr = 0;                        // reset for next graph replay
        }
    }
}

extern "C" void kernel_launch(void* const* d_in, const int* in_sizes, int n_in,
                              void* d_out, int out_size) {
    const float* yp = (const float*)d_in[0];   // y_pred [N, 32]
    const float* yt = (const float*)d_in[1];   // y_true [N, 32]
    const int N = in_sizes[0] / 32;
    const int nblocks = N / 8;

    gram_mma<<<NCTA, TPB>>>(yp, yt, nblocks);
    reduce_final<<<NOUT / 4, TPB>>>((float*)d_out, 1.0f / (float)N);
}